// round 6
// baseline (speedup 1.0000x reference)
#include <cuda_runtime.h>
#include <cuda_bf16.h>
#include <math.h>

#define NLAYERS 12
#define DMODEL  256
#define DINNER  512
#define DTRANK  16
#define DSTATE  16
#define INDIM   230
#define BATCH   4096
#define ROWS    16
#define NTHREADS 512

#define KT1 16    // 256/16 k-tiles, GEMM1
#define NT1 128   // 1024/8 n-tiles, GEMM1
#define KT3 32    // 512/16 k-tiles, GEMM3
#define NT3 32    // 256/8  n-tiles, GEMM3
#define KT2 32    // 512/16 k-tiles, GEMM2
#define NT2 6     // 48/8   n-tiles, GEMM2
#define NG1 (NLAYERS*KT1*NT1*32)   // 786432
#define NG3 (NLAYERS*KT3*NT3*32)   // 393216
#define NG2 (NLAYERS*KT2*NT2*32)   // 73728

// fragment-packed weights: uint4 = (hi.reg0, hi.reg1, lo.reg0, lo.reg1)
__device__ uint4 g_W1[NG1];
__device__ uint4 g_W3[NG3];
__device__ uint4 g_W2[NG2];

// ---------------------------------------------------------------------------
union F2 { float2 f; unsigned long long u; };
__device__ __forceinline__ void ffma2(F2 &d, const F2 a, const F2 b) {
    asm("fma.rn.f32x2 %0, %1, %2, %0;" : "+l"(d.u) : "l"(a.u), "l"(b.u));
}
__device__ __forceinline__ F2 bcast2(float v) { F2 r; r.f = make_float2(v, v); return r; }

__device__ __forceinline__ float silu_f(float v) {
    return v * (1.0f / (1.0f + __expf(-v)));
}
__device__ __forceinline__ float softplus_f(float v) {
    return (v > 20.0f) ? v : log1pf(__expf(v));
}

__device__ __forceinline__ void split2(float x, float y, unsigned &hi, unsigned &lo) {
    __nv_bfloat162 h = __floats2bfloat162_rn(x, y);
    float rx = x - __bfloat162float(__low2bfloat16(h));
    float ry = y - __bfloat162float(__high2bfloat16(h));
    __nv_bfloat162 l2 = __floats2bfloat162_rn(rx, ry);
    hi = *reinterpret_cast<unsigned*>(&h);
    lo = *reinterpret_cast<unsigned*>(&l2);
}
__device__ __forceinline__ float2 bf2f2(unsigned p) {
    __nv_bfloat162 b = *reinterpret_cast<__nv_bfloat162*>(&p);
    return __bfloat1622float2(b);
}

__device__ __forceinline__ void mma_bf16(float (&d)[4], const unsigned (&a)[4],
                                         unsigned b0, unsigned b1) {
    asm volatile(
        "mma.sync.aligned.m16n8k16.row.col.f32.bf16.bf16.f32 "
        "{%0,%1,%2,%3}, {%4,%5,%6,%7}, {%8,%9}, {%0,%1,%2,%3};"
        : "+f"(d[0]), "+f"(d[1]), "+f"(d[2]), "+f"(d[3])
        : "r"(a[0]), "r"(a[1]), "r"(a[2]), "r"(a[3]), "r"(b0), "r"(b1));
}

// 3-term bf16-split mma: hi*hi + lo*hi + hi*lo
__device__ __forceinline__ void mma3(float (&d)[4], const unsigned (&ahi)[4],
                                     const unsigned (&alo)[4], uint4 W) {
    mma_bf16(d, ahi, W.x, W.y);
    mma_bf16(d, alo, W.x, W.y);
    mma_bf16(d, ahi, W.z, W.w);
}

// ---------------------------------------------------------------------------
// prep: repack weights into mma B-fragment order, bf16 hi/lo, uint4-merged
// ---------------------------------------------------------------------------
extern "C" __global__ void prep_kernel(const float* __restrict__ in_proj_w,
                                       const float* __restrict__ out_proj_w,
                                       const float* __restrict__ x_proj_w)
{
    int gid = blockIdx.x * blockDim.x + threadIdx.x;
    const float* W; int ncols, NTx, KTx, idx;
    uint4* dst;
    if (gid < NG1) {
        idx = gid; W = in_proj_w; ncols = 1024; NTx = NT1; KTx = KT1; dst = g_W1;
    } else if (gid < NG1 + NG3) {
        idx = gid - NG1; W = out_proj_w; ncols = DMODEL; NTx = NT3; KTx = KT3; dst = g_W3;
    } else if (gid < NG1 + NG3 + NG2) {
        idx = gid - NG1 - NG3; W = x_proj_w; ncols = 48; NTx = NT2; KTx = KT2; dst = g_W2;
    } else return;

    int lane = idx & 31; int rest = idx >> 5;
    int nt = rest % NTx; rest /= NTx;
    int kt = rest % KTx; int l = rest / KTx;
    int n  = nt * 8 + (lane >> 2);
    int k0 = kt * 16 + (lane & 3) * 2;
    const float* Wl = W + (size_t)l * (NTx == NT1 ? DMODEL : DINNER) * ncols;
    float v0 = Wl[(size_t)(k0    ) * ncols + n];
    float v1 = Wl[(size_t)(k0 + 1) * ncols + n];
    float v2 = Wl[(size_t)(k0 + 8) * ncols + n];
    float v3 = Wl[(size_t)(k0 + 9) * ncols + n];
    unsigned h0, l0, h1, l1;
    split2(v0, v1, h0, l0);
    split2(v2, v3, h1, l1);
    dst[idx] = make_uint4(h0, h1, l0, l1);
}

// ---------------------------------------------------------------------------
// main: one block = 16 batch rows, 512 threads, 2 CTAs/SM (32 warps/SM).
// Activation A-fragments (bf16 hi/lo) live in SMEM:
//   (row r, col pair c): kt=c/16, lane=(r%8)*4+(c%8)/2, reg=(r/8)+2*((c%16)/8)
// SMEM: sh_h(4096f) sh_z(8192f) dblA(768f) dblB(768f) bc(16f)
//       hfrag hi/lo (2x2048u) xyfrag hi/lo (2x4096u)  = 104512 B
// ---------------------------------------------------------------------------
extern "C" __global__ void __launch_bounds__(NTHREADS, 2)
mamba_icl_kernel(const float* __restrict__ x,
                 const float* __restrict__ Wi,
                 const float* __restrict__ bi,
                 const float* __restrict__ conv_w,
                 const float* __restrict__ conv_b,
                 const float* __restrict__ dt_proj_w,
                 const float* __restrict__ dt_proj_b,
                 const float* __restrict__ Dvec,
                 const float* __restrict__ Wo,
                 const float* __restrict__ bo,
                 float* __restrict__ out)
{
    extern __shared__ float sm[];
    float*    sh_h      = sm;                    // 4096
    float*    sh_z      = sm + 4096;             // 8192
    float*    sh_dblA   = sm + 12288;            // 768
    float*    sh_dblB   = sm + 13056;            // 768
    float*    sh_bc     = sm + 13824;            // 16
    unsigned* hfrag_hi  = (unsigned*)(sm + 13840);   // 2048
    unsigned* hfrag_lo  = hfrag_hi + 2048;           // 2048
    unsigned* xyfrag_hi = hfrag_lo + 2048;           // 4096
    unsigned* xyfrag_lo = xyfrag_hi + 4096;          // 4096

    const int t    = threadIdx.x;
    const int row0 = blockIdx.x * ROWS;
    const int wid  = t >> 5;          // 0..15
    const int lane = t & 31;
    const int fr   = lane >> 2;
    const int fc   = (lane & 3) * 2;

    // ---- stage x into sh_z scratch ----
    float* sh_x = sh_z;
    for (int idx = t; idx < ROWS * INDIM; idx += NTHREADS) {
        int r = idx / INDIM, c = idx - r * INDIM;
        sh_x[r * INDIM + c] = x[(size_t)(row0 + r) * INDIM + c];
    }
    __syncthreads();

    // ---- input projection -> h-frags (fp32 FFMA2, one-time) ----
    {
        const int tx = t & 127;           // col pair group (2 cols)
        const int ty = t >> 7;            // 0..3 -> 4 rows each
        F2 acc[4];
        #pragma unroll
        for (int i = 0; i < 4; i++) acc[i].f = make_float2(0.f, 0.f);
        const int rbase = ty * 4;
        #pragma unroll 2
        for (int k0 = 0; k0 < INDIM; k0 += 2) {
            F2 w0; w0.f = *(const float2*)(Wi + (size_t)k0 * DMODEL + tx * 2);
            F2 w1; w1.f = *(const float2*)(Wi + (size_t)(k0 + 1) * DMODEL + tx * 2);
            #pragma unroll
            for (int i = 0; i < 4; i++) {
                float2 a2 = *(const float2*)(sh_x + (rbase + i) * INDIM + k0);
                ffma2(acc[i], bcast2(a2.x), w0);
                ffma2(acc[i], bcast2(a2.y), w1);
            }
        }
        __syncthreads();   // done with sh_x
        float2 bv = *(const float2*)(bi + tx * 2);
        const int kt = tx >> 3;
        #pragma unroll
        for (int i = 0; i < 4; i++) {
            int row = rbase + i;
            unsigned hh, ll;
            split2(acc[i].f.x + bv.x, acc[i].f.y + bv.y, hh, ll);
            int idx = (kt * 32 + (row & 7) * 4 + (tx & 3)) * 4
                      + (row >> 3) + 2 * ((tx >> 2) & 1);
            hfrag_hi[idx] = hh;
            hfrag_lo[idx] = ll;
        }
    }
    __syncthreads();

    for (int l = 0; l < NLAYERS; l++) {
        const float* Cw = conv_w    + (size_t)l * DINNER * 4;
        const float* Cb = conv_b    + (size_t)l * DINNER;
        const float* Dw = dt_proj_w + (size_t)l * DTRANK * DINNER;
        const float* Db = dt_proj_b + (size_t)l * DINNER;
        const float* Dd = Dvec      + (size_t)l * DINNER;

        // ================= GEMM1: [16,256]@[256,1024], 8 n-tiles/warp ======
        {
            float acc[8][4];
            #pragma unroll
            for (int nt = 0; nt < 8; nt++)
                #pragma unroll
                for (int j = 0; j < 4; j++) acc[nt][j] = 0.f;

            for (int kt = 0; kt < KT1; kt++) {
                unsigned ahi[4], alo[4];
                *(uint4*)ahi = *(const uint4*)&hfrag_hi[(kt * 32 + lane) * 4];
                *(uint4*)alo = *(const uint4*)&hfrag_lo[(kt * 32 + lane) * 4];
                const uint4* bw = g_W1 + (((size_t)l * KT1 + kt) * NT1 + wid * 8) * 32 + lane;
                #pragma unroll
                for (int nt = 0; nt < 8; nt++)
                    mma3(acc[nt], ahi, alo, bw[nt * 32]);
            }
            // epilogue: warps 0-7 -> xc frags; warps 8-15 -> silu(z) fp32
            if (wid < 8) {
                #pragma unroll
                for (int nt = 0; nt < 8; nt++) {
                    int c = wid * 64 + nt * 8 + fc;
                    float cw0 = Cw[c * 4 + 3],       cb0 = Cb[c];
                    float cw1 = Cw[(c + 1) * 4 + 3], cb1 = Cb[c + 1];
                    float v00 = silu_f(acc[nt][0] * cw0 + cb0);
                    float v01 = silu_f(acc[nt][1] * cw1 + cb1);
                    float v10 = silu_f(acc[nt][2] * cw0 + cb0);
                    float v11 = silu_f(acc[nt][3] * cw1 + cb1);
                    unsigned h0, l0, h1, l1;
                    split2(v00, v01, h0, l0);
                    split2(v10, v11, h1, l1);
                    int idx = ((c >> 4) * 32 + lane) * 4 + 2 * (nt & 1);
                    *(uint2*)&xyfrag_hi[idx] = make_uint2(h0, h1);
                    *(uint2*)&xyfrag_lo[idx] = make_uint2(l0, l1);
                }
            } else {
                #pragma unroll
                for (int nt = 0; nt < 8; nt++) {
                    int c = (wid - 8) * 64 + nt * 8 + fc;
                    *(float2*)&sh_z[fr * 512 + c] =
                        make_float2(silu_f(acc[nt][0]), silu_f(acc[nt][1]));
                    *(float2*)&sh_z[(fr + 8) * 512 + c] =
                        make_float2(silu_f(acc[nt][2]), silu_f(acc[nt][3]));
                }
            }
        }
        __syncthreads();

        // ===== GEMM2: dbl = xc @ x_proj [16,512]@[512,48], 12 warps k-split =
        if (wid < 12) {
            const int nt2 = wid % 6;
            const int kh  = wid / 6;
            float d[4] = {0.f, 0.f, 0.f, 0.f};
            const int ktb = kh * 16;
            for (int kk = 0; kk < 16; kk++) {
                int kt = ktb + kk;
                unsigned ahi[4], alo[4];
                *(uint4*)ahi = *(const uint4*)&xyfrag_hi[(kt * 32 + lane) * 4];
                *(uint4*)alo = *(const uint4*)&xyfrag_lo[(kt * 32 + lane) * 4];
                uint4 W = g_W2[(((size_t)l * KT2 + kt) * NT2 + nt2) * 32 + lane];
                mma3(d, ahi, alo, W);
            }
            float* dbl = kh ? sh_dblB : sh_dblA;
            int c = nt2 * 8 + fc;
            *(float2*)&dbl[fr * 48 + c]       = make_float2(d[0], d[1]);
            *(float2*)&dbl[(fr + 8) * 48 + c] = make_float2(d[2], d[3]);
        }
        __syncthreads();

        // ---- bc[r] = dot(B, C) over D_STATE (partials summed) ----
        if (t < ROWS) {
            float s = 0.f;
            #pragma unroll
            for (int j = 0; j < DSTATE; j++) {
                float bmv = sh_dblA[t * 48 + DTRANK + j] + sh_dblB[t * 48 + DTRANK + j];
                float cmv = sh_dblA[t * 48 + DTRANK + DSTATE + j] + sh_dblB[t * 48 + DTRANK + DSTATE + j];
                s = fmaf(bmv, cmv, s);
            }
            sh_bc[t] = s;
        }
        __syncthreads();

        // ---- gating: y = xc*(softplus(dt)*bc + D)*silu(z), in-place frags --
        {
            const int cp   = t & 255;          // col pair index
            const int half = t >> 8;           // 0/1 -> rows 0-7 / 8-15
            const int c    = cp * 2;
            const int ktg  = cp >> 3;
            const int rb   = 2 * ((cp >> 2) & 1);
            F2 dw[DTRANK];
            #pragma unroll
            for (int j = 0; j < DTRANK; j++)
                dw[j].f = *(const float2*)(Dw + j * DINNER + c);
            const float2 dbv = *(const float2*)(Db + c);
            const float2 ddv = *(const float2*)(Dd + c);

            #pragma unroll 2
            for (int rr = 0; rr < 8; rr++) {
                int r = half * 8 + rr;
                float4 a0 = *(const float4*)(sh_dblA + r * 48);
                float4 b0 = *(const float4*)(sh_dblB + r * 48);
                float4 a1 = *(const float4*)(sh_dblA + r * 48 + 4);
                float4 b1 = *(const float4*)(sh_dblB + r * 48 + 4);
                float4 a2 = *(const float4*)(sh_dblA + r * 48 + 8);
                float4 b2 = *(const float4*)(sh_dblB + r * 48 + 8);
                float4 a3 = *(const float4*)(sh_dblA + r * 48 + 12);
                float4 b3 = *(const float4*)(sh_dblB + r * 48 + 12);
                F2 sdt; sdt.f = dbv;
                ffma2(sdt, bcast2(a0.x + b0.x), dw[0]);  ffma2(sdt, bcast2(a0.y + b0.y), dw[1]);
                ffma2(sdt, bcast2(a0.z + b0.z), dw[2]);  ffma2(sdt, bcast2(a0.w + b0.w), dw[3]);
                ffma2(sdt, bcast2(a1.x + b1.x), dw[4]);  ffma2(sdt, bcast2(a1.y + b1.y), dw[5]);
                ffma2(sdt, bcast2(a1.z + b1.z), dw[6]);  ffma2(sdt, bcast2(a1.w + b1.w), dw[7]);
                ffma2(sdt, bcast2(a2.x + b2.x), dw[8]);  ffma2(sdt, bcast2(a2.y + b2.y), dw[9]);
                ffma2(sdt, bcast2(a2.z + b2.z), dw[10]); ffma2(sdt, bcast2(a2.w + b2.w), dw[11]);
                ffma2(sdt, bcast2(a3.x + b3.x), dw[12]); ffma2(sdt, bcast2(a3.y + b3.y), dw[13]);
                ffma2(sdt, bcast2(a3.z + b3.z), dw[14]); ffma2(sdt, bcast2(a3.w + b3.w), dw[15]);
                float dt0 = softplus_f(sdt.f.x);
                float dt1 = softplus_f(sdt.f.y);
                float bcr = sh_bc[r];

                int idx = (ktg * 32 + (r & 7) * 4 + (cp & 3)) * 4 + rb + (r >> 3);
                float2 xh = bf2f2(xyfrag_hi[idx]);
                float2 xl = bf2f2(xyfrag_lo[idx]);
                float2 sz = *(const float2*)&sh_z[r * 512 + c];
                float y0 = (xh.x + xl.x) * (dt0 * bcr + ddv.x) * sz.x;
                float y1 = (xh.y + xl.y) * (dt1 * bcr + ddv.y) * sz.y;
                unsigned nh, nl;
                split2(y0, y1, nh, nl);
                xyfrag_hi[idx] = nh;
                xyfrag_lo[idx] = nl;
            }
        }
        __syncthreads();

        // ================= GEMM3: h = y @ out_proj, 2 n-tiles/warp =========
        {
            float acc3[2][4];
            #pragma unroll
            for (int nt = 0; nt < 2; nt++)
                #pragma unroll
                for (int j = 0; j < 4; j++) acc3[nt][j] = 0.f;

            for (int kt = 0; kt < KT3; kt++) {
                unsigned ahi[4], alo[4];
                *(uint4*)ahi = *(const uint4*)&xyfrag_hi[(kt * 32 + lane) * 4];
                *(uint4*)alo = *(const uint4*)&xyfrag_lo[(kt * 32 + lane) * 4];
                const uint4* bw = g_W3 + (((size_t)l * KT3 + kt) * NT3 + wid * 2) * 32 + lane;
                mma3(acc3[0], ahi, alo, bw[0]);
                mma3(acc3[1], ahi, alo, bw[32]);
            }
            // epilogue: h-frags (next GEMM1) + fp32 h (head)
            #pragma unroll
            for (int nt = 0; nt < 2; nt++) {
                int c = wid * 16 + nt * 8 + fc;
                unsigned h0, l0, h1, l1;
                split2(acc3[nt][0], acc3[nt][1], h0, l0);
                split2(acc3[nt][2], acc3[nt][3], h1, l1);
                int idx = ((c >> 4) * 32 + lane) * 4 + 2 * nt;
                *(uint2*)&hfrag_hi[idx] = make_uint2(h0, h1);
                *(uint2*)&hfrag_lo[idx] = make_uint2(l0, l1);
                *(float2*)&sh_h[fr * DMODEL + c]       = make_float2(acc3[nt][0], acc3[nt][1]);
                *(float2*)&sh_h[(fr + 8) * DMODEL + c] = make_float2(acc3[nt][2], acc3[nt][3]);
            }
        }
        __syncthreads();
    }

    // ---- output head ----
    if (t < ROWS) {
        float s = 0.f;
        #pragma unroll 8
        for (int m = 0; m < DMODEL; m++)
            s = fmaf(sh_h[t * DMODEL + m], Wo[m], s);
        out[row0 + t] = s + bo[0];
    }
}

// ---------------------------------------------------------------------------
extern "C" void kernel_launch(void* const* d_in, const int* in_sizes, int n_in,
                              void* d_out, int out_size)
{
    (void)in_sizes; (void)n_in; (void)out_size;

    prep_kernel<<<(NG1 + NG3 + NG2 + 255) / 256, 256>>>(
        (const float*)d_in[3],    // in_proj_w
        (const float*)d_in[11],   // out_proj_w
        (const float*)d_in[6]);   // x_proj_w

    const size_t smem_bytes = (size_t)(13856 + 2048 * 2 + 4096 * 2) * 4;  // 104576

    cudaFuncSetAttribute(mamba_icl_kernel,
                         cudaFuncAttributeMaxDynamicSharedMemorySize,
                         (int)smem_bytes);

    mamba_icl_kernel<<<BATCH / ROWS, NTHREADS, smem_bytes>>>(
        (const float*)d_in[0],   // x
        (const float*)d_in[1],   // Wi
        (const float*)d_in[2],   // bi
        (const float*)d_in[4],   // conv_w
        (const float*)d_in[5],   // conv_b
        (const float*)d_in[7],   // dt_proj_w
        (const float*)d_in[8],   // dt_proj_b
        // d_in[9] = A_log dead (h0 = 0, L = 1)
        (const float*)d_in[10],  // D
        (const float*)d_in[12],  // Wo
        (const float*)d_in[13],  // bo
        (float*)d_out);
}